// round 10
// baseline (speedup 1.0000x reference)
#include <cuda_runtime.h>
#include <math.h>
#include <stdint.h>

#define C 16
#define D 512
#define CHUNK_ROWS 128
#define DPB 256            // dims per block-half in pass 1
#define NPAIRS (C*(C-1)/2)
#define NCHUNK 512         // row chunks (N=65536 / 128)
#define PBLK (NCHUNK*2)    // pass-1 partial blocks = 1024
#define GRPS 64            // stage-A groups
#define CPG (NCHUNK/GRPS)  // chunks per group = 8

// ---------------- device scratch (no allocations allowed) ----------------
__device__ float2 g_partial[PBLK * C * DPB];     // 32 MB
__device__ float2 g_pA[GRPS * C * D];            // 4 MB
__device__ int    g_order[NCHUNK * CHUNK_ROWS];  // sorted (row | class<<16)
__device__ int    g_choff[NCHUNK * 17];          // per-chunk class offsets
__device__ int    g_counts[C];
__device__ float  g_mean[C * D];
__device__ float  g_within[C * D];
__device__ float  g_lnB[NPAIRS];
__device__ double g_pairsum[NPAIRS];
__device__ int    g_ids_is64;

__device__ __forceinline__ int get_id(const int* ids32, int i, int is64) {
    return is64 ? ids32[2 * i] : ids32[i];    // little-endian low word
}

__device__ __forceinline__ int detect_is64(const int* ids32, int n) {
    int lim = n / 2; if (lim > 64) lim = 64;
    int any = 0;
    for (int i = 0; i < lim; i++) any |= ids32[2 * i + 1];
    return any == 0;
}

// ---------------- init ----------------
__global__ void k_init() {
    if (threadIdx.x < C) g_counts[threadIdx.x] = 0;
}

// ---------------- class counts (+ publish dtype flag) ----------------
__global__ void k_counts(const int* __restrict__ ids32, int n) {
    __shared__ int loc[C];
    __shared__ int s_is64;
    if (threadIdx.x < C) loc[threadIdx.x] = 0;
    if (threadIdx.x == 0) {
        int is64 = detect_is64(ids32, n);
        s_is64 = is64;
        if (blockIdx.x == 0) g_ids_is64 = is64;
    }
    __syncthreads();
    int is64 = s_is64;
    for (int i = blockIdx.x * blockDim.x + threadIdx.x; i < n;
         i += gridDim.x * blockDim.x) {
        int c = get_id(ids32, i, is64) & (C - 1);
        atomicAdd(&loc[c], 1);
    }
    __syncthreads();
    if (threadIdx.x < C) atomicAdd(&g_counts[threadIdx.x], loc[threadIdx.x]);
}

// ---------------- per-chunk class-sorted order (deterministic) -------------
// 128 rows per chunk, 128 threads (4 warps). Warp-level rank via match_any;
// cross-warp via per-warp histograms. Block 0 also precomputes the pair lnB.
__global__ __launch_bounds__(128) void k_order(const int* __restrict__ ids32) {
    __shared__ int s_whist[4][C];
    __shared__ int s_wbase[4][C];
    __shared__ int s_hist[C];
    __shared__ int s_off[17];
    int t = threadIdx.x;
    int w = t >> 5, lane = t & 31;
    int chunk = blockIdx.x;

    if (t < 4 * C) ((int*)s_whist)[t] = 0;
    int c = get_id(ids32, chunk * CHUNK_ROWS + t, g_ids_is64) & (C - 1);
    __syncthreads();

    unsigned mask = __match_any_sync(0xffffffffu, c);
    int lr = __popc(mask & ((1u << lane) - 1u));
    if (lr == 0) s_whist[w][c] = __popc(mask);
    __syncthreads();

    if (t < C) {
        int acc = 0;
#pragma unroll
        for (int ww = 0; ww < 4; ww++) { s_wbase[ww][t] = acc; acc += s_whist[ww][t]; }
        s_hist[t] = acc;
    }
    __syncthreads();
    if (t == 0) {
        int acc = 0;
#pragma unroll
        for (int cc = 0; cc < C; cc++) { s_off[cc] = acc; acc += s_hist[cc]; }
        s_off[C] = acc;
    }
    __syncthreads();

    int pos = s_off[c] + s_wbase[w][c] + lr;
    g_order[chunk * CHUNK_ROWS + pos] = t | (c << 16);
    if (t < 17) g_choff[chunk * 17 + t] = s_off[t];

    // folded lnB precompute (block 0 only; uses finalized g_counts)
    if (blockIdx.x == 0 && t < NPAIRS) {
        int i = 0, rem = t;
        while (rem >= C - 1 - i) { rem -= C - 1 - i; i++; }
        float ni = (float)g_counts[i], nj = (float)g_counts[i + 1 + rem];
        float pc = ni + nj;
        float d2 = pc - 2.f;
        if (d2 == 0.f) d2 = 1e-5f;
        double bd = (double)(d2 * 0.5f);
        g_lnB[t] = (float)(lgamma(0.5) + lgamma(bd) - lgamma(0.5 + bd));
    }
}

// ---------------- pass 1: sorted-order streaming, register accumulators ----
// block = (chunk of 128 rows) x (half of the 512 dims). 1024 blocks ->
// ~7 blocks/SM resident (68 B smem), ~55 warps/SM. Register accumulate,
// flush on class change (block-uniform branch), 8-wide batched loads.
#define P1STEP(pp, vv)                                              \
    {                                                               \
        int cc = (pp) >> 16;                                        \
        if (cc != cur) {                                            \
            out[cur * DPB] = make_float2(s, q);                     \
            s = 0.f; q = 0.f; cur = cc;                             \
        }                                                           \
        s += (vv); q = fmaf((vv), (vv), q);                         \
    }

__global__ __launch_bounds__(256) void k_pass1(const float* __restrict__ hidden) {
    __shared__ int s_off[17];
    int t = threadIdx.x;
    int half  = blockIdx.x & 1;
    int chunk = blockIdx.x >> 1;
    if (t < 17) s_off[t] = g_choff[chunk * 17 + t];
    __syncthreads();

    const float* base = hidden + (size_t)chunk * CHUNK_ROWS * D + half * DPB + t;
    const int*   ord  = g_order + chunk * CHUNK_ROWS;
    float2*      out  = g_partial + (size_t)blockIdx.x * (C * DPB) + t;

    float s = 0.f, q = 0.f;
    int cur = ord[0] >> 16;
#pragma unroll 1
    for (int k = 0; k < CHUNK_ROWS; k += 8) {
        int p0 = ord[k + 0], p1 = ord[k + 1], p2 = ord[k + 2], p3 = ord[k + 3];
        int p4 = ord[k + 4], p5 = ord[k + 5], p6 = ord[k + 6], p7 = ord[k + 7];
        float v0 = base[(size_t)(p0 & 0xffff) * D];
        float v1 = base[(size_t)(p1 & 0xffff) * D];
        float v2 = base[(size_t)(p2 & 0xffff) * D];
        float v3 = base[(size_t)(p3 & 0xffff) * D];
        float v4 = base[(size_t)(p4 & 0xffff) * D];
        float v5 = base[(size_t)(p5 & 0xffff) * D];
        float v6 = base[(size_t)(p6 & 0xffff) * D];
        float v7 = base[(size_t)(p7 & 0xffff) * D];
        P1STEP(p0, v0) P1STEP(p1, v1) P1STEP(p2, v2) P1STEP(p3, v3)
        P1STEP(p4, v4) P1STEP(p5, v5) P1STEP(p6, v6) P1STEP(p7, v7)
    }
    out[cur * DPB] = make_float2(s, q);
#pragma unroll
    for (int cc = 0; cc < C; cc++)
        if (s_off[cc + 1] == s_off[cc]) out[cc * DPB] = make_float2(0.f, 0.f);
}

// ---------------- pass 2 stage A: wide coalesced partial reduction ---------
__global__ __launch_bounds__(256) void k_pass2a() {
    int gid  = blockIdx.x * 256 + threadIdx.x;     // 0 .. 524287
    int item = gid & (C * D - 1);                  // 0 .. 8191
    int grp  = gid >> 13;                          // 0 .. 63
    int c    = item >> 9;
    int dim  = item & (D - 1);
    int half = dim >> 8;
    int t    = dim & (DPB - 1);
    const float2* p = g_partial + (size_t)c * DPB + t;
    float sx = 0.f, qq = 0.f;
#pragma unroll
    for (int k = 0; k < CPG; k++) {
        int chunk = grp * CPG + k;                 // 0 .. 511
        int blk   = (chunk << 1) | half;           // 0 .. 1023
        float2 v = p[(size_t)blk * (C * DPB)];
        sx += v.x; qq += v.y;
    }
    g_pA[grp * (C * D) + item] = make_float2(sx, qq);
}

// ---------------- pass 2 stage B: fp64 final -> mean / within --------------
__global__ __launch_bounds__(256) void k_pass2b() {
    int item = blockIdx.x * 256 + threadIdx.x;     // 0 .. 8191
    double sa = 0, sb = 0, qa = 0, qb = 0;
#pragma unroll
    for (int g = 0; g < GRPS; g += 2) {
        float2 v0 = g_pA[(g + 0) * (C * D) + item];
        float2 v1 = g_pA[(g + 1) * (C * D) + item];
        sa += (double)v0.x; qa += (double)v0.y;
        sb += (double)v1.x; qb += (double)v1.y;
    }
    double sx = sa + sb, qq = qa + qb;
    int c = item >> 9;
    double cnt  = (double)g_counts[c];
    double mean = sx / cnt;
    g_mean[item]   = (float)mean;
    g_within[item] = (float)(qq - sx * mean);
}

// ---------------- fp32 Lentz continued fraction for betainc ----------------
__device__ float betacf_f(float a, float b, float x) {
    const float FPMIN = 1e-30f;
    float qab = a + b, qap = a + 1.f, qam = a - 1.f;
    float cc = 1.f;
    float dd = 1.f - qab * x / qap;
    if (fabsf(dd) < FPMIN) dd = FPMIN;
    dd = 1.f / dd;
    float h = dd;
    for (int m = 1; m <= 250; m++) {
        float fm = (float)m, m2 = 2.f * fm;
        float aa = fm * (b - fm) * x / ((qam + m2) * (a + m2));
        dd = 1.f + aa * dd; if (fabsf(dd) < FPMIN) dd = FPMIN;
        cc = 1.f + aa / cc; if (fabsf(cc) < FPMIN) cc = FPMIN;
        dd = 1.f / dd;
        h *= dd * cc;
        aa = -(a + fm) * (qab + fm) * x / ((a + m2) * (qap + m2));
        dd = 1.f + aa * dd; if (fabsf(dd) < FPMIN) dd = FPMIN;
        cc = 1.f + aa / cc; if (fabsf(cc) < FPMIN) cc = FPMIN;
        dd = 1.f / dd;
        float del = dd * cc;
        h *= del;
        if (fabsf(del - 1.f) < 1e-7f) break;
    }
    return h;
}

// ---------------- pair kernel: x -> sort -> betainc(top-K) -> sum log ------
__global__ __launch_bounds__(D) void k_pairs(const int* __restrict__ dptr) {
    __shared__ float sx[D];
    __shared__ float sred[D];
    int t = threadIdx.x;

    int bid = blockIdx.x;
    int i = 0, rem = bid;
    while (rem >= C - 1 - i) { rem -= C - 1 - i; i++; }
    int j = i + 1 + rem;

    float ni = (float)g_counts[i], nj = (float)g_counts[j];
    float pc = ni + nj;
    float d2 = pc - 2.f;
    if (d2 == 0.f) d2 = 1e-5f;
    float b = d2 * 0.5f;

    float mi = g_mean[i * D + t],  mj = g_mean[j * D + t];
    float wi = g_within[i * D + t], wj = g_within[j * D + t];
    float hd   = (mi - mj) * 0.5f;
    float betw = hd * hd * pc;
    float x = betw / (betw + wi + wj);
    x = fminf(fmaxf(x, 1e-37f), 1.f - 1e-5f);
    sx[t] = x;
    __syncthreads();

    for (int k = 2; k <= D; k <<= 1) {
        for (int jj = k >> 1; jj > 0; jj >>= 1) {
            int ixj = t ^ jj;
            if (ixj > t) {
                float a0 = sx[t], b0 = sx[ixj];
                bool desc = ((t & k) == 0);
                if (desc ? (a0 < b0) : (a0 > b0)) { sx[t] = b0; sx[ixj] = a0; }
            }
            __syncthreads();
        }
    }

    int K = 64;
    if (dptr) {
        int kv = dptr[0];
        if (kv >= 1 && kv <= D) K = kv;
    }

    const float a = 0.5f;
    float val = 0.f;
    if (t < K) {
        float xv  = sx[t];
        float lnB = g_lnB[bid];
        float lbt = a * logf(xv) + b * log1pf(-xv) - lnB;
        float thresh = (a + 1.f) / (a + b + 2.f);
        float logI;
        if (xv < thresh) {
            float cf = betacf_f(a, b, xv);
            if (cf < 1e-30f) cf = 1e-30f;
            logI = lbt + logf(cf) - logf(a);
        } else {
            float cf   = betacf_f(b, a, 1.f - xv);
            float tail = expf(lbt) * cf / b;
            if (tail > 0.99999994f) tail = 0.99999994f;
            logI = log1pf(-tail);
        }
        val = logI;
    }
    sred[t] = val;
    __syncthreads();
    for (int s = D / 2; s > 0; s >>= 1) {
        if (t < s) sred[t] += sred[t + s];
        __syncthreads();
    }
    if (t == 0) g_pairsum[bid] = (double)sred[0];
}

// ---------------- final scalar reduce (parallel, fixed tree order) ---------
__global__ void k_final(float* out) {
    __shared__ double sr[128];
    int t = threadIdx.x;
    sr[t] = (t < NPAIRS) ? g_pairsum[t] : 0.0;
    __syncthreads();
    for (int s = 64; s > 0; s >>= 1) {
        if (t < s) sr[t] += sr[t + s];
        __syncthreads();
    }
    if (t == 0) out[0] = (float)(-sr[0]);
}

// ---------------- launch ----------------
extern "C" void kernel_launch(void* const* d_in, const int* in_sizes, int n_in,
                              void* d_out, int out_size) {
    const float* hidden = (const float*)d_in[0];
    const int*   ids32  = (const int*)d_in[1];
    const int*   dptr   = (n_in > 2) ? (const int*)d_in[2] : nullptr;

    int N = in_sizes[0] / D;            // 65536

    k_init  <<<1, 32>>>();                               // launch 1
    k_counts<<<128, 256>>>(ids32, N);                    // launch 2
    k_order <<<NCHUNK, 128>>>(ids32);                    // launch 3
    k_pass1 <<<PBLK, 256>>>(hidden);                     // launch 4 (profiled)
    k_pass2a<<<(GRPS * C * D) / 256, 256>>>();           // launch 5
    k_pass2b<<<(C * D) / 256, 256>>>();                  // launch 6
    k_pairs <<<NPAIRS, D>>>(dptr);                       // launch 7
    k_final <<<1, 128>>>((float*)d_out);                 // launch 8
}

// round 11
// speedup vs baseline: 1.0156x; 1.0156x over previous
#include <cuda_runtime.h>
#include <math.h>
#include <stdint.h>

#define C 16
#define D 512
#define CHUNK_ROWS 128
#define DPB 256            // dims per block-half in pass 1
#define NPAIRS (C*(C-1)/2)
#define NCHUNK 512         // row chunks (N=65536 / 128)
#define PBLK (NCHUNK*2)    // pass-1 partial blocks = 1024
#define GRPS 64            // stage-A groups
#define CPG (NCHUNK/GRPS)  // chunks per group = 8

// ---------------- device scratch (no allocations allowed) ----------------
__device__ float2 g_partial[PBLK * C * DPB];     // 32 MB
__device__ float2 g_pA[GRPS * C * D];            // 4 MB
__device__ int    g_order[NCHUNK * CHUNK_ROWS];  // sorted (row | class<<16)
__device__ int    g_choff[NCHUNK * 17];          // per-chunk class offsets
__device__ int    g_chunkhist[NCHUNK * C];       // per-chunk class histogram
__device__ int    g_counts[C];
__device__ float  g_lnB[NPAIRS];
__device__ double g_pairsum[NPAIRS];

__device__ __forceinline__ int get_id(const int* ids32, int i, int is64) {
    return is64 ? ids32[2 * i] : ids32[i];    // little-endian low word
}

__device__ __forceinline__ int detect_is64(const int* ids32, int n) {
    int lim = n / 2; if (lim > 64) lim = 64;
    int any = 0;
    for (int i = 0; i < lim; i++) any |= ids32[2 * i + 1];
    return any == 0;
}

// ---------------- launch 1: per-chunk class-sorted order (deterministic) ---
// 128 rows per chunk, 128 threads (4 warps). Local dtype detect per block.
// Writes order, class offsets, and the per-chunk histogram.
__global__ __launch_bounds__(128) void k_order(const int* __restrict__ ids32,
                                               int n) {
    __shared__ int s_whist[4][C];
    __shared__ int s_wbase[4][C];
    __shared__ int s_hist[C];
    __shared__ int s_off[17];
    __shared__ int s_is64;
    int t = threadIdx.x;
    int w = t >> 5, lane = t & 31;
    int chunk = blockIdx.x;

    if (t < 4 * C) ((int*)s_whist)[t] = 0;
    if (t == 0) s_is64 = detect_is64(ids32, n);
    __syncthreads();
    int c = get_id(ids32, chunk * CHUNK_ROWS + t, s_is64) & (C - 1);

    unsigned mask = __match_any_sync(0xffffffffu, c);
    int lr = __popc(mask & ((1u << lane) - 1u));
    if (lr == 0) s_whist[w][c] = __popc(mask);
    __syncthreads();

    if (t < C) {
        int acc = 0;
#pragma unroll
        for (int ww = 0; ww < 4; ww++) { s_wbase[ww][t] = acc; acc += s_whist[ww][t]; }
        s_hist[t] = acc;
    }
    __syncthreads();
    if (t == 0) {
        int acc = 0;
#pragma unroll
        for (int cc = 0; cc < C; cc++) { s_off[cc] = acc; acc += s_hist[cc]; }
        s_off[C] = acc;
    }
    __syncthreads();

    int pos = s_off[c] + s_wbase[w][c] + lr;
    g_order[chunk * CHUNK_ROWS + pos] = t | (c << 16);
    if (t < 17) g_choff[chunk * 17 + t] = s_off[t];
    if (t < C)  g_chunkhist[chunk * C + t] = s_hist[t];
}

// ---------------- launch 2: pass 1 + (block 0) counts & lnB ---------------
#define P1STEP(pp, vv)                                              \
    {                                                               \
        int cc = (pp) >> 16;                                        \
        if (cc != cur) {                                            \
            out[cur * DPB] = make_float2(s, q);                     \
            s = 0.f; q = 0.f; cur = cc;                             \
        }                                                           \
        s += (vv); q = fmaf((vv), (vv), q);                         \
    }

__global__ __launch_bounds__(256) void k_pass1(const float* __restrict__ hidden) {
    __shared__ int s_off[17];
    __shared__ int s_cnt[256];
    int t = threadIdx.x;

    // block 0: reduce chunk histograms -> g_counts, then lnB (fp64 lgamma)
    if (blockIdx.x == 0) {
        int c = t & 15, seg = t >> 4;            // 16 segments x 16 classes
        int acc = 0;
        for (int ch = seg; ch < NCHUNK; ch += 16) acc += g_chunkhist[ch * C + c];
        s_cnt[t] = acc;
        __syncthreads();
        if (t < C) {
            int tot = 0;
#pragma unroll
            for (int s2 = 0; s2 < 16; s2++) tot += s_cnt[s2 * 16 + t];
            g_counts[t] = tot;
            s_cnt[t] = tot;                       // reuse for lnB below
        }
        __syncthreads();
        if (t < NPAIRS) {
            int i = 0, rem = t;
            while (rem >= C - 1 - i) { rem -= C - 1 - i; i++; }
            float ni = (float)s_cnt[i], nj = (float)s_cnt[i + 1 + rem];
            float pc = ni + nj;
            float d2 = pc - 2.f;
            if (d2 == 0.f) d2 = 1e-5f;
            double bd = (double)(d2 * 0.5f);
            g_lnB[t] = (float)(lgamma(0.5) + lgamma(bd) - lgamma(0.5 + bd));
        }
        __syncthreads();
    }

    int half  = blockIdx.x & 1;
    int chunk = blockIdx.x >> 1;
    if (t < 17) s_off[t] = g_choff[chunk * 17 + t];
    __syncthreads();

    const float* base = hidden + (size_t)chunk * CHUNK_ROWS * D + half * DPB + t;
    const int*   ord  = g_order + chunk * CHUNK_ROWS;
    float2*      out  = g_partial + (size_t)blockIdx.x * (C * DPB) + t;

    float s = 0.f, q = 0.f;
    int cur = ord[0] >> 16;
#pragma unroll 1
    for (int k = 0; k < CHUNK_ROWS; k += 8) {
        int p0 = ord[k + 0], p1 = ord[k + 1], p2 = ord[k + 2], p3 = ord[k + 3];
        int p4 = ord[k + 4], p5 = ord[k + 5], p6 = ord[k + 6], p7 = ord[k + 7];
        float v0 = base[(size_t)(p0 & 0xffff) * D];
        float v1 = base[(size_t)(p1 & 0xffff) * D];
        float v2 = base[(size_t)(p2 & 0xffff) * D];
        float v3 = base[(size_t)(p3 & 0xffff) * D];
        float v4 = base[(size_t)(p4 & 0xffff) * D];
        float v5 = base[(size_t)(p5 & 0xffff) * D];
        float v6 = base[(size_t)(p6 & 0xffff) * D];
        float v7 = base[(size_t)(p7 & 0xffff) * D];
        P1STEP(p0, v0) P1STEP(p1, v1) P1STEP(p2, v2) P1STEP(p3, v3)
        P1STEP(p4, v4) P1STEP(p5, v5) P1STEP(p6, v6) P1STEP(p7, v7)
    }
    out[cur * DPB] = make_float2(s, q);
#pragma unroll
    for (int cc = 0; cc < C; cc++)
        if (s_off[cc + 1] == s_off[cc]) out[cc * DPB] = make_float2(0.f, 0.f);
}

// ---------------- launch 3: pass 2 stage A (wide coalesced) ----------------
__global__ __launch_bounds__(256) void k_pass2a() {
    int gid  = blockIdx.x * 256 + threadIdx.x;     // 0 .. 524287
    int item = gid & (C * D - 1);                  // 0 .. 8191
    int grp  = gid >> 13;                          // 0 .. 63
    int c    = item >> 9;
    int dim  = item & (D - 1);
    int half = dim >> 8;
    int t    = dim & (DPB - 1);
    const float2* p = g_partial + (size_t)c * DPB + t;
    float sx = 0.f, qq = 0.f;
#pragma unroll
    for (int k = 0; k < CPG; k++) {
        int chunk = grp * CPG + k;                 // 0 .. 511
        int blk   = (chunk << 1) | half;           // 0 .. 1023
        float2 v = p[(size_t)blk * (C * DPB)];
        sx += v.x; qq += v.y;
    }
    g_pA[grp * (C * D) + item] = make_float2(sx, qq);
}

// ---------------- fp32 Lentz continued fraction (fast divisions) -----------
__device__ float betacf_f(float a, float b, float x) {
    const float FPMIN = 1e-30f;
    float qab = a + b, qap = a + 1.f, qam = a - 1.f;
    float cc = 1.f;
    float dd = 1.f - qab * x / qap;
    if (fabsf(dd) < FPMIN) dd = FPMIN;
    dd = __fdividef(1.f, dd);
    float h = dd;
    for (int m = 1; m <= 250; m++) {
        float fm = (float)m, m2 = 2.f * fm;
        float aa = fm * (b - fm) * x / ((qam + m2) * (a + m2));
        dd = 1.f + aa * dd; if (fabsf(dd) < FPMIN) dd = FPMIN;
        cc = 1.f + __fdividef(aa, cc); if (fabsf(cc) < FPMIN) cc = FPMIN;
        dd = __fdividef(1.f, dd);
        h *= dd * cc;
        aa = -(a + fm) * (qab + fm) * x / ((a + m2) * (qap + m2));
        dd = 1.f + aa * dd; if (fabsf(dd) < FPMIN) dd = FPMIN;
        cc = 1.f + __fdividef(aa, cc); if (fabsf(cc) < FPMIN) cc = FPMIN;
        dd = __fdividef(1.f, dd);
        float del = dd * cc;
        h *= del;
        if (fabsf(del - 1.f) < 1e-7f) break;
    }
    return h;
}

// ---------------- launch 4 (PROFILED): pair kernel --------------------------
// Folds the old pass2b: per-dim stats for classes i,j reduced from g_pA
// (fp64, 2-way split, same order as before), then x -> sort -> betainc -> sum.
__global__ __launch_bounds__(D) void k_pairs(const int* __restrict__ dptr) {
    __shared__ float sx[D];
    __shared__ float sred[D];
    int t = threadIdx.x;

    int bid = blockIdx.x;
    int i = 0, rem = bid;
    while (rem >= C - 1 - i) { rem -= C - 1 - i; i++; }
    int j = i + 1 + rem;

    float ni = (float)g_counts[i], nj = (float)g_counts[j];
    float pc = ni + nj;
    float d2 = pc - 2.f;
    if (d2 == 0.f) d2 = 1e-5f;
    float b = d2 * 0.5f;

    // per-dim stats (mirrors old pass2b exactly: 2-way split fp64)
    double sa, sb2, qa, qb;
    sa = sb2 = qa = qb = 0.0;
#pragma unroll
    for (int g = 0; g < GRPS; g += 2) {
        float2 v0 = g_pA[(g + 0) * (C * D) + i * D + t];
        float2 v1 = g_pA[(g + 1) * (C * D) + i * D + t];
        sa += (double)v0.x; qa += (double)v0.y;
        sb2 += (double)v1.x; qb += (double)v1.y;
    }
    double sxi = sa + sb2, qqi = qa + qb;
    double mi_d = sxi / (double)g_counts[i];
    float mi = (float)mi_d;
    float wi = (float)(qqi - sxi * mi_d);

    sa = sb2 = qa = qb = 0.0;
#pragma unroll
    for (int g = 0; g < GRPS; g += 2) {
        float2 v0 = g_pA[(g + 0) * (C * D) + j * D + t];
        float2 v1 = g_pA[(g + 1) * (C * D) + j * D + t];
        sa += (double)v0.x; qa += (double)v0.y;
        sb2 += (double)v1.x; qb += (double)v1.y;
    }
    double sxj = sa + sb2, qqj = qa + qb;
    double mj_d = sxj / (double)g_counts[j];
    float mj = (float)mj_d;
    float wj = (float)(qqj - sxj * mj_d);

    float hd   = (mi - mj) * 0.5f;
    float betw = hd * hd * pc;
    float x = betw / (betw + wi + wj);
    x = fminf(fmaxf(x, 1e-37f), 1.f - 1e-5f);
    sx[t] = x;
    __syncthreads();

    for (int k = 2; k <= D; k <<= 1) {
        for (int jj = k >> 1; jj > 0; jj >>= 1) {
            int ixj = t ^ jj;
            if (ixj > t) {
                float a0 = sx[t], b0 = sx[ixj];
                bool desc = ((t & k) == 0);
                if (desc ? (a0 < b0) : (a0 > b0)) { sx[t] = b0; sx[ixj] = a0; }
            }
            __syncthreads();
        }
    }

    int K = 64;
    if (dptr) {
        int kv = dptr[0];
        if (kv >= 1 && kv <= D) K = kv;
    }

    const float a = 0.5f;
    float val = 0.f;
    if (t < K) {
        float xv  = sx[t];
        float lnB = g_lnB[bid];
        float lbt = a * logf(xv) + b * log1pf(-xv) - lnB;
        float thresh = (a + 1.f) / (a + b + 2.f);
        float logI;
        if (xv < thresh) {
            float cf = betacf_f(a, b, xv);
            if (cf < 1e-30f) cf = 1e-30f;
            logI = lbt + logf(cf) - logf(a);
        } else {
            float cf   = betacf_f(b, a, 1.f - xv);
            float tail = expf(lbt) * cf / b;
            if (tail > 0.99999994f) tail = 0.99999994f;
            logI = log1pf(-tail);
        }
        val = logI;
    }
    sred[t] = val;
    __syncthreads();
    for (int s = D / 2; s > 0; s >>= 1) {
        if (t < s) sred[t] += sred[t + s];
        __syncthreads();
    }
    if (t == 0) g_pairsum[bid] = (double)sred[0];
}

// ---------------- launch 5: final scalar reduce -----------------------------
__global__ void k_final(float* out) {
    __shared__ double sr[128];
    int t = threadIdx.x;
    sr[t] = (t < NPAIRS) ? g_pairsum[t] : 0.0;
    __syncthreads();
    for (int s = 64; s > 0; s >>= 1) {
        if (t < s) sr[t] += sr[t + s];
        __syncthreads();
    }
    if (t == 0) out[0] = (float)(-sr[0]);
}

// ---------------- launch ----------------
extern "C" void kernel_launch(void* const* d_in, const int* in_sizes, int n_in,
                              void* d_out, int out_size) {
    const float* hidden = (const float*)d_in[0];
    const int*   ids32  = (const int*)d_in[1];
    const int*   dptr   = (n_in > 2) ? (const int*)d_in[2] : nullptr;

    int N = in_sizes[0] / D;            // 65536

    k_order <<<NCHUNK, 128>>>(ids32, N);                 // launch 1
    k_pass1 <<<PBLK, 256>>>(hidden);                     // launch 2
    k_pass2a<<<(GRPS * C * D) / 256, 256>>>();           // launch 3
    k_pairs <<<NPAIRS, D>>>(dptr);                       // launch 4 (profiled)
    k_final <<<1, 128>>>((float*)d_out);                 // launch 5
}

// round 12
// speedup vs baseline: 1.0946x; 1.0778x over previous
#include <cuda_runtime.h>
#include <math.h>
#include <stdint.h>

#define C 16
#define D 512
#define CHUNK_ROWS 128
#define DPB 256            // dims per block-half in pass 1
#define NPAIRS (C*(C-1)/2)
#define NCHUNK 512         // row chunks (N=65536 / 128)
#define PBLK (NCHUNK*2)    // pass-1 partial blocks = 1024
#define GRPS 64            // stage-A groups
#define CPG (NCHUNK/GRPS)  // chunks per group = 8

// ---------------- device scratch (no allocations allowed) ----------------
__device__ float2 g_partial[PBLK * C * DPB];     // 32 MB
__device__ float2 g_pA[GRPS * C * D];            // 4 MB
__device__ int    g_order[NCHUNK * CHUNK_ROWS];  // sorted (row | class<<16)
__device__ int    g_choff[NCHUNK * 17];          // per-chunk class offsets
__device__ int    g_chunkhist[NCHUNK * C];       // per-chunk class histogram
__device__ int    g_counts[C];
__device__ double g_pairsum[NPAIRS];

__device__ __forceinline__ int get_id(const int* ids32, int i, int is64) {
    return is64 ? ids32[2 * i] : ids32[i];    // little-endian low word
}

__device__ __forceinline__ int detect_is64(const int* ids32, int n) {
    int lim = n / 2; if (lim > 64) lim = 64;
    int any = 0;
    for (int i = 0; i < lim; i++) any |= ids32[2 * i + 1];
    return any == 0;
}

// ---------------- launch 1: per-chunk class-sorted order (deterministic) ---
__global__ __launch_bounds__(128) void k_order(const int* __restrict__ ids32,
                                               int n) {
    __shared__ int s_whist[4][C];
    __shared__ int s_wbase[4][C];
    __shared__ int s_hist[C];
    __shared__ int s_off[17];
    __shared__ int s_is64;
    int t = threadIdx.x;
    int w = t >> 5, lane = t & 31;
    int chunk = blockIdx.x;

    if (t < 4 * C) ((int*)s_whist)[t] = 0;
    if (t == 0) s_is64 = detect_is64(ids32, n);
    __syncthreads();
    int c = get_id(ids32, chunk * CHUNK_ROWS + t, s_is64) & (C - 1);

    unsigned mask = __match_any_sync(0xffffffffu, c);
    int lr = __popc(mask & ((1u << lane) - 1u));
    if (lr == 0) s_whist[w][c] = __popc(mask);
    __syncthreads();

    if (t < C) {
        int acc = 0;
#pragma unroll
        for (int ww = 0; ww < 4; ww++) { s_wbase[ww][t] = acc; acc += s_whist[ww][t]; }
        s_hist[t] = acc;
    }
    __syncthreads();
    if (t == 0) {
        int acc = 0;
#pragma unroll
        for (int cc = 0; cc < C; cc++) { s_off[cc] = acc; acc += s_hist[cc]; }
        s_off[C] = acc;
    }
    __syncthreads();

    int pos = s_off[c] + s_wbase[w][c] + lr;
    g_order[chunk * CHUNK_ROWS + pos] = t | (c << 16);
    if (t < 17) g_choff[chunk * 17 + t] = s_off[t];
    if (t < C)  g_chunkhist[chunk * C + t] = s_hist[t];
}

// ---------------- launch 2: pass 1 + (block 0) counts reduction ------------
#define P1STEP(pp, vv)                                              \
    {                                                               \
        int cc = (pp) >> 16;                                        \
        if (cc != cur) {                                            \
            out[cur * DPB] = make_float2(s, q);                     \
            s = 0.f; q = 0.f; cur = cc;                             \
        }                                                           \
        s += (vv); q = fmaf((vv), (vv), q);                         \
    }

__global__ __launch_bounds__(256) void k_pass1(const float* __restrict__ hidden) {
    __shared__ int s_off[17];
    __shared__ int s_cnt[256];
    int t = threadIdx.x;

    // block 0: reduce chunk histograms -> g_counts
    if (blockIdx.x == 0) {
        int c = t & 15, seg = t >> 4;            // 16 segments x 16 classes
        int acc = 0;
        for (int ch = seg; ch < NCHUNK; ch += 16) acc += g_chunkhist[ch * C + c];
        s_cnt[t] = acc;
        __syncthreads();
        if (t < C) {
            int tot = 0;
#pragma unroll
            for (int s2 = 0; s2 < 16; s2++) tot += s_cnt[s2 * 16 + t];
            g_counts[t] = tot;
        }
        __syncthreads();
    }

    int half  = blockIdx.x & 1;
    int chunk = blockIdx.x >> 1;
    if (t < 17) s_off[t] = g_choff[chunk * 17 + t];
    __syncthreads();

    const float* base = hidden + (size_t)chunk * CHUNK_ROWS * D + half * DPB + t;
    const int*   ord  = g_order + chunk * CHUNK_ROWS;
    float2*      out  = g_partial + (size_t)blockIdx.x * (C * DPB) + t;

    float s = 0.f, q = 0.f;
    int cur = ord[0] >> 16;
#pragma unroll 1
    for (int k = 0; k < CHUNK_ROWS; k += 8) {
        int p0 = ord[k + 0], p1 = ord[k + 1], p2 = ord[k + 2], p3 = ord[k + 3];
        int p4 = ord[k + 4], p5 = ord[k + 5], p6 = ord[k + 6], p7 = ord[k + 7];
        float v0 = base[(size_t)(p0 & 0xffff) * D];
        float v1 = base[(size_t)(p1 & 0xffff) * D];
        float v2 = base[(size_t)(p2 & 0xffff) * D];
        float v3 = base[(size_t)(p3 & 0xffff) * D];
        float v4 = base[(size_t)(p4 & 0xffff) * D];
        float v5 = base[(size_t)(p5 & 0xffff) * D];
        float v6 = base[(size_t)(p6 & 0xffff) * D];
        float v7 = base[(size_t)(p7 & 0xffff) * D];
        P1STEP(p0, v0) P1STEP(p1, v1) P1STEP(p2, v2) P1STEP(p3, v3)
        P1STEP(p4, v4) P1STEP(p5, v5) P1STEP(p6, v6) P1STEP(p7, v7)
    }
    out[cur * DPB] = make_float2(s, q);
#pragma unroll
    for (int cc = 0; cc < C; cc++)
        if (s_off[cc + 1] == s_off[cc]) out[cc * DPB] = make_float2(0.f, 0.f);
}

// ---------------- launch 3: pass 2 stage A (wide coalesced) ----------------
__global__ __launch_bounds__(256) void k_pass2a() {
    int gid  = blockIdx.x * 256 + threadIdx.x;     // 0 .. 524287
    int item = gid & (C * D - 1);                  // 0 .. 8191
    int grp  = gid >> 13;                          // 0 .. 63
    int c    = item >> 9;
    int dim  = item & (D - 1);
    int half = dim >> 8;
    int t    = dim & (DPB - 1);
    const float2* p = g_partial + (size_t)c * DPB + t;
    float sx = 0.f, qq = 0.f;
#pragma unroll
    for (int k = 0; k < CPG; k++) {
        int chunk = grp * CPG + k;                 // 0 .. 511
        int blk   = (chunk << 1) | half;           // 0 .. 1023
        float2 v = p[(size_t)blk * (C * DPB)];
        sx += v.x; qq += v.y;
    }
    g_pA[grp * (C * D) + item] = make_float2(sx, qq);
}

// ---------------- launch 4: pair kernel -------------------------------------
// Per-dim stats for classes i,j reduced from g_pA (fp64, 2-way split), then
// x -> bitonic sort -> large-b asymptotic log-betainc on top-K -> sum.
// I_x(1/2,b) = erf(sqrt(s)) - sqrt(s)e^{-s}/(4b sqrt(pi)) + O(1/b^2),
// s = -b*log1p(-x). Monotone in x, so top-k commutes with the transform.
__global__ __launch_bounds__(D) void k_pairs(const int* __restrict__ dptr) {
    __shared__ float sx[D];
    __shared__ float sred[D];
    int t = threadIdx.x;

    int bid = blockIdx.x;
    int i = 0, rem = bid;
    while (rem >= C - 1 - i) { rem -= C - 1 - i; i++; }
    int j = i + 1 + rem;

    float ni = (float)g_counts[i], nj = (float)g_counts[j];
    float pc = ni + nj;
    float d2 = pc - 2.f;
    if (d2 == 0.f) d2 = 1e-5f;
    float b = d2 * 0.5f;

    // per-dim stats (fp64, 2-way split, fixed order)
    double sa, sb2, qa, qb;
    sa = sb2 = qa = qb = 0.0;
#pragma unroll
    for (int g = 0; g < GRPS; g += 2) {
        float2 v0 = g_pA[(g + 0) * (C * D) + i * D + t];
        float2 v1 = g_pA[(g + 1) * (C * D) + i * D + t];
        sa += (double)v0.x; qa += (double)v0.y;
        sb2 += (double)v1.x; qb += (double)v1.y;
    }
    double sxi = sa + sb2, qqi = qa + qb;
    double mi_d = sxi / (double)g_counts[i];
    float mi = (float)mi_d;
    float wi = (float)(qqi - sxi * mi_d);

    sa = sb2 = qa = qb = 0.0;
#pragma unroll
    for (int g = 0; g < GRPS; g += 2) {
        float2 v0 = g_pA[(g + 0) * (C * D) + j * D + t];
        float2 v1 = g_pA[(g + 1) * (C * D) + j * D + t];
        sa += (double)v0.x; qa += (double)v0.y;
        sb2 += (double)v1.x; qb += (double)v1.y;
    }
    double sxj = sa + sb2, qqj = qa + qb;
    double mj_d = sxj / (double)g_counts[j];
    float mj = (float)mj_d;
    float wj = (float)(qqj - sxj * mj_d);

    float hd   = (mi - mj) * 0.5f;
    float betw = hd * hd * pc;
    float x = betw / (betw + wi + wj);
    x = fminf(fmaxf(x, 1e-37f), 1.f - 1e-5f);
    sx[t] = x;
    __syncthreads();

    for (int k = 2; k <= D; k <<= 1) {
        for (int jj = k >> 1; jj > 0; jj >>= 1) {
            int ixj = t ^ jj;
            if (ixj > t) {
                float a0 = sx[t], b0 = sx[ixj];
                bool desc = ((t & k) == 0);
                if (desc ? (a0 < b0) : (a0 > b0)) { sx[t] = b0; sx[ixj] = a0; }
            }
            __syncthreads();
        }
    }

    int K = 64;
    if (dptr) {
        int kv = dptr[0];
        if (kv >= 1 && kv <= D) K = kv;
    }

    float val = 0.f;
    if (t < K) {
        float xv = sx[t];
        float s2 = -b * log1pf(-xv);               // s = -b ln(1-x)
        float rs = sqrtf(s2);
        const float inv_sqrtpi = 0.5641895835477563f;  // 1/sqrt(pi)
        float I = erff(rs) - rs * expf(-s2) * (inv_sqrtpi * 0.25f / b);
        I = fminf(fmaxf(I, 1e-38f), 1.f);
        val = logf(I);
    }
    sred[t] = val;
    __syncthreads();
    for (int s = D / 2; s > 0; s >>= 1) {
        if (t < s) sred[t] += sred[t + s];
        __syncthreads();
    }
    if (t == 0) g_pairsum[bid] = (double)sred[0];
}

// ---------------- launch 5: final scalar reduce -----------------------------
__global__ void k_final(float* out) {
    __shared__ double sr[128];
    int t = threadIdx.x;
    sr[t] = (t < NPAIRS) ? g_pairsum[t] : 0.0;
    __syncthreads();
    for (int s = 64; s > 0; s >>= 1) {
        if (t < s) sr[t] += sr[t + s];
        __syncthreads();
    }
    if (t == 0) out[0] = (float)(-sr[0]);
}

// ---------------- launch ----------------
extern "C" void kernel_launch(void* const* d_in, const int* in_sizes, int n_in,
                              void* d_out, int out_size) {
    const float* hidden = (const float*)d_in[0];
    const int*   ids32  = (const int*)d_in[1];
    const int*   dptr   = (n_in > 2) ? (const int*)d_in[2] : nullptr;

    int N = in_sizes[0] / D;            // 65536

    k_order <<<NCHUNK, 128>>>(ids32, N);                 // launch 1
    k_pass1 <<<PBLK, 256>>>(hidden);                     // launch 2
    k_pass2a<<<(GRPS * C * D) / 256, 256>>>();           // launch 3
    k_pairs <<<NPAIRS, D>>>(dptr);                       // launch 4 (profiled)
    k_final <<<1, 128>>>((float*)d_out);                 // launch 5
}

// round 13
// speedup vs baseline: 2.3847x; 2.1786x over previous
#include <cuda_runtime.h>
#include <math.h>
#include <stdint.h>

#define C 16
#define D 512
#define CHUNK_ROWS 128
#define DPB 256            // dims per block-half in pass 1
#define NPAIRS (C*(C-1)/2)
#define NCHUNK 512         // row chunks (N=65536 / 128)
#define PBLK (NCHUNK*2)    // pass-1 partial blocks = 1024
#define GRPS 64            // stage-A groups
#define CPG (NCHUNK/GRPS)  // chunks per group = 8

// ---------------- device scratch (no allocations allowed) ----------------
__device__ float2 g_partial[PBLK * C * DPB];     // 32 MB
__device__ float2 g_pA[GRPS * C * D];            // 4 MB
__device__ int    g_order[NCHUNK * CHUNK_ROWS];  // sorted (row | class<<16)
__device__ int    g_choff[NCHUNK * 17];          // per-chunk class offsets
__device__ int    g_chunkhist[NCHUNK * C];       // per-chunk class histogram
__device__ int    g_counts[C];
__device__ double g_pairsum[NPAIRS];

__device__ __forceinline__ int get_id(const int* ids32, int i, int is64) {
    return is64 ? ids32[2 * i] : ids32[i];    // little-endian low word
}

__device__ __forceinline__ int detect_is64(const int* ids32, int n) {
    int lim = n / 2; if (lim > 64) lim = 64;
    int any = 0;
    for (int i = 0; i < lim; i++) any |= ids32[2 * i + 1];
    return any == 0;
}

// ---------------- launch 1: per-chunk class-sorted order (deterministic) ---
__global__ __launch_bounds__(128) void k_order(const int* __restrict__ ids32,
                                               int n) {
    __shared__ int s_whist[4][C];
    __shared__ int s_wbase[4][C];
    __shared__ int s_hist[C];
    __shared__ int s_off[17];
    __shared__ int s_is64;
    int t = threadIdx.x;
    int w = t >> 5, lane = t & 31;
    int chunk = blockIdx.x;

    if (t < 4 * C) ((int*)s_whist)[t] = 0;
    if (t == 0) s_is64 = detect_is64(ids32, n);
    __syncthreads();
    int c = get_id(ids32, chunk * CHUNK_ROWS + t, s_is64) & (C - 1);

    unsigned mask = __match_any_sync(0xffffffffu, c);
    int lr = __popc(mask & ((1u << lane) - 1u));
    if (lr == 0) s_whist[w][c] = __popc(mask);
    __syncthreads();

    if (t < C) {
        int acc = 0;
#pragma unroll
        for (int ww = 0; ww < 4; ww++) { s_wbase[ww][t] = acc; acc += s_whist[ww][t]; }
        s_hist[t] = acc;
    }
    __syncthreads();
    if (t == 0) {
        int acc = 0;
#pragma unroll
        for (int cc = 0; cc < C; cc++) { s_off[cc] = acc; acc += s_hist[cc]; }
        s_off[C] = acc;
    }
    __syncthreads();

    int pos = s_off[c] + s_wbase[w][c] + lr;
    g_order[chunk * CHUNK_ROWS + pos] = t | (c << 16);
    if (t < 17) g_choff[chunk * 17 + t] = s_off[t];
    if (t < C)  g_chunkhist[chunk * C + t] = s_hist[t];
}

// ---------------- launch 2: pass 1 + (block 0) counts reduction ------------
#define P1STEP(pp, vv)                                              \
    {                                                               \
        int cc = (pp) >> 16;                                        \
        if (cc != cur) {                                            \
            out[cur * DPB] = make_float2(s, q);                     \
            s = 0.f; q = 0.f; cur = cc;                             \
        }                                                           \
        s += (vv); q = fmaf((vv), (vv), q);                         \
    }

__global__ __launch_bounds__(256) void k_pass1(const float* __restrict__ hidden) {
    __shared__ int s_off[17];
    __shared__ int s_cnt[256];
    int t = threadIdx.x;

    // block 0: reduce chunk histograms -> g_counts
    if (blockIdx.x == 0) {
        int c = t & 15, seg = t >> 4;            // 16 segments x 16 classes
        int acc = 0;
        for (int ch = seg; ch < NCHUNK; ch += 16) acc += g_chunkhist[ch * C + c];
        s_cnt[t] = acc;
        __syncthreads();
        if (t < C) {
            int tot = 0;
#pragma unroll
            for (int s2 = 0; s2 < 16; s2++) tot += s_cnt[s2 * 16 + t];
            g_counts[t] = tot;
        }
        __syncthreads();
    }

    int half  = blockIdx.x & 1;
    int chunk = blockIdx.x >> 1;
    if (t < 17) s_off[t] = g_choff[chunk * 17 + t];
    __syncthreads();

    const float* base = hidden + (size_t)chunk * CHUNK_ROWS * D + half * DPB + t;
    const int*   ord  = g_order + chunk * CHUNK_ROWS;
    float2*      out  = g_partial + (size_t)blockIdx.x * (C * DPB) + t;

    float s = 0.f, q = 0.f;
    int cur = ord[0] >> 16;
#pragma unroll 1
    for (int k = 0; k < CHUNK_ROWS; k += 8) {
        int p0 = ord[k + 0], p1 = ord[k + 1], p2 = ord[k + 2], p3 = ord[k + 3];
        int p4 = ord[k + 4], p5 = ord[k + 5], p6 = ord[k + 6], p7 = ord[k + 7];
        float v0 = base[(size_t)(p0 & 0xffff) * D];
        float v1 = base[(size_t)(p1 & 0xffff) * D];
        float v2 = base[(size_t)(p2 & 0xffff) * D];
        float v3 = base[(size_t)(p3 & 0xffff) * D];
        float v4 = base[(size_t)(p4 & 0xffff) * D];
        float v5 = base[(size_t)(p5 & 0xffff) * D];
        float v6 = base[(size_t)(p6 & 0xffff) * D];
        float v7 = base[(size_t)(p7 & 0xffff) * D];
        P1STEP(p0, v0) P1STEP(p1, v1) P1STEP(p2, v2) P1STEP(p3, v3)
        P1STEP(p4, v4) P1STEP(p5, v5) P1STEP(p6, v6) P1STEP(p7, v7)
    }
    out[cur * DPB] = make_float2(s, q);
#pragma unroll
    for (int cc = 0; cc < C; cc++)
        if (s_off[cc + 1] == s_off[cc]) out[cc * DPB] = make_float2(0.f, 0.f);
}

// ---------------- launch 3: pass 2 stage A (wide coalesced) ----------------
__global__ __launch_bounds__(256) void k_pass2a() {
    int gid  = blockIdx.x * 256 + threadIdx.x;     // 0 .. 524287
    int item = gid & (C * D - 1);                  // 0 .. 8191
    int grp  = gid >> 13;                          // 0 .. 63
    int c    = item >> 9;
    int dim  = item & (D - 1);
    int half = dim >> 8;
    int t    = dim & (DPB - 1);
    const float2* p = g_partial + (size_t)c * DPB + t;
    float sx = 0.f, qq = 0.f;
#pragma unroll
    for (int k = 0; k < CPG; k++) {
        int chunk = grp * CPG + k;                 // 0 .. 511
        int blk   = (chunk << 1) | half;           // 0 .. 1023
        float2 v = p[(size_t)blk * (C * DPB)];
        sx += v.x; qq += v.y;
    }
    g_pA[grp * (C * D) + item] = make_float2(sx, qq);
}

// ---------------- launch 4: pair kernel (fp32 stats, no fp64 pipe) ---------
// Per-dim stats for classes i,j reduced from g_pA in fp32 (2-way split),
// then x -> bitonic sort -> large-b asymptotic log-betainc on top-K -> sum.
// I_x(1/2,b) = erf(sqrt(s)) - sqrt(s)e^{-s}/(4b sqrt(pi)) + O(1/b^2),
// s = -b*log1p(-x). Monotone in x, so top-k commutes with the transform.
__global__ __launch_bounds__(D) void k_pairs(const int* __restrict__ dptr) {
    __shared__ float sx[D];
    __shared__ float sred[D];
    int t = threadIdx.x;

    int bid = blockIdx.x;
    int i = 0, rem = bid;
    while (rem >= C - 1 - i) { rem -= C - 1 - i; i++; }
    int j = i + 1 + rem;

    float ni = (float)g_counts[i], nj = (float)g_counts[j];
    float pc = ni + nj;
    float d2 = pc - 2.f;
    if (d2 == 0.f) d2 = 1e-5f;
    float b = d2 * 0.5f;

    // per-dim stats, fp32 2-way split accumulation (fixed order)
    float sa, sb2, qa, qb;
    sa = sb2 = qa = qb = 0.f;
#pragma unroll
    for (int g = 0; g < GRPS; g += 2) {
        float2 v0 = g_pA[(g + 0) * (C * D) + i * D + t];
        float2 v1 = g_pA[(g + 1) * (C * D) + i * D + t];
        sa += v0.x; qa += v0.y;
        sb2 += v1.x; qb += v1.y;
    }
    float sxi = sa + sb2, qqi = qa + qb;
    float mi = sxi / ni;
    float wi = qqi - sxi * mi;

    sa = sb2 = qa = qb = 0.f;
#pragma unroll
    for (int g = 0; g < GRPS; g += 2) {
        float2 v0 = g_pA[(g + 0) * (C * D) + j * D + t];
        float2 v1 = g_pA[(g + 1) * (C * D) + j * D + t];
        sa += v0.x; qa += v0.y;
        sb2 += v1.x; qb += v1.y;
    }
    float sxj = sa + sb2, qqj = qa + qb;
    float mj = sxj / nj;
    float wj = qqj - sxj * mj;

    float hd   = (mi - mj) * 0.5f;
    float betw = hd * hd * pc;
    float x = betw / (betw + wi + wj);
    x = fminf(fmaxf(x, 1e-37f), 1.f - 1e-5f);
    sx[t] = x;
    __syncthreads();

    for (int k = 2; k <= D; k <<= 1) {
        for (int jj = k >> 1; jj > 0; jj >>= 1) {
            int ixj = t ^ jj;
            if (ixj > t) {
                float a0 = sx[t], b0 = sx[ixj];
                bool desc = ((t & k) == 0);
                if (desc ? (a0 < b0) : (a0 > b0)) { sx[t] = b0; sx[ixj] = a0; }
            }
            __syncthreads();
        }
    }

    int K = 64;
    if (dptr) {
        int kv = dptr[0];
        if (kv >= 1 && kv <= D) K = kv;
    }

    float val = 0.f;
    if (t < K) {
        float xv = sx[t];
        float s2 = -b * log1pf(-xv);               // s = -b ln(1-x)
        float rs = sqrtf(s2);
        const float inv_sqrtpi = 0.5641895835477563f;  // 1/sqrt(pi)
        float I = erff(rs) - rs * expf(-s2) * (inv_sqrtpi * 0.25f / b);
        I = fminf(fmaxf(I, 1e-38f), 1.f);
        val = logf(I);
    }
    sred[t] = val;
    __syncthreads();
    for (int s = D / 2; s > 0; s >>= 1) {
        if (t < s) sred[t] += sred[t + s];
        __syncthreads();
    }
    if (t == 0) g_pairsum[bid] = (double)sred[0];
}

// ---------------- launch 5: final scalar reduce -----------------------------
__global__ void k_final(float* out) {
    __shared__ double sr[128];
    int t = threadIdx.x;
    sr[t] = (t < NPAIRS) ? g_pairsum[t] : 0.0;
    __syncthreads();
    for (int s = 64; s > 0; s >>= 1) {
        if (t < s) sr[t] += sr[t + s];
        __syncthreads();
    }
    if (t == 0) out[0] = (float)(-sr[0]);
}

// ---------------- launch ----------------
extern "C" void kernel_launch(void* const* d_in, const int* in_sizes, int n_in,
                              void* d_out, int out_size) {
    const float* hidden = (const float*)d_in[0];
    const int*   ids32  = (const int*)d_in[1];
    const int*   dptr   = (n_in > 2) ? (const int*)d_in[2] : nullptr;

    int N = in_sizes[0] / D;            // 65536

    k_order <<<NCHUNK, 128>>>(ids32, N);                 // launch 1
    k_pass1 <<<PBLK, 256>>>(hidden);                     // launch 2
    k_pass2a<<<(GRPS * C * D) / 256, 256>>>();           // launch 3
    k_pairs <<<NPAIRS, D>>>(dptr);                       // launch 4 (profiled)
    k_final <<<1, 128>>>((float*)d_out);                 // launch 5
}

// round 14
// speedup vs baseline: 2.4903x; 1.0443x over previous
#include <cuda_runtime.h>
#include <math.h>
#include <stdint.h>

#define C 16
#define D 512
#define CHUNK_ROWS 256
#define DPQ 128            // dims per quarter-block in pass 1
#define NPAIRS (C*(C-1)/2)
#define NCHUNK 256         // row chunks (N=65536 / 256)
#define PBLK (NCHUNK*4)    // pass-1 partial blocks = 1024 (4 dim-quarters)
#define GRPS 8             // stage-A groups
#define CPG (NCHUNK/GRPS)  // chunks per group = 32

// ---------------- device scratch (no allocations allowed) ----------------
__device__ float2 g_partial[PBLK * C * DPQ];     // 16 MB
__device__ float2 g_pA[GRPS * C * D];            // 512 KB (L2-resident)
__device__ int    g_order[NCHUNK * CHUNK_ROWS];  // sorted (row | class<<16)
__device__ int    g_choff[NCHUNK * 17];          // per-chunk class offsets
__device__ int    g_chunkhist[NCHUNK * C];       // per-chunk class histogram
__device__ int    g_counts[C];
__device__ double g_pairsum[NPAIRS];

__device__ __forceinline__ int get_id(const int* ids32, int i, int is64) {
    return is64 ? ids32[2 * i] : ids32[i];    // little-endian low word
}

__device__ __forceinline__ int detect_is64(const int* ids32, int n) {
    int lim = n / 2; if (lim > 64) lim = 64;
    int any = 0;
    for (int i = 0; i < lim; i++) any |= ids32[2 * i + 1];
    return any == 0;
}

// ---------------- launch 1: per-chunk class-sorted order (deterministic) ---
// 256 rows per chunk, 256 threads (8 warps). Warp-level rank via match_any.
__global__ __launch_bounds__(256) void k_order(const int* __restrict__ ids32,
                                               int n) {
    __shared__ int s_whist[8][C];
    __shared__ int s_wbase[8][C];
    __shared__ int s_hist[C];
    __shared__ int s_off[17];
    __shared__ int s_is64;
    int t = threadIdx.x;
    int w = t >> 5, lane = t & 31;
    int chunk = blockIdx.x;

    if (t < 8 * C) ((int*)s_whist)[t] = 0;
    if (t == 0) s_is64 = detect_is64(ids32, n);
    __syncthreads();
    int c = get_id(ids32, chunk * CHUNK_ROWS + t, s_is64) & (C - 1);

    unsigned mask = __match_any_sync(0xffffffffu, c);
    int lr = __popc(mask & ((1u << lane) - 1u));
    if (lr == 0) s_whist[w][c] = __popc(mask);
    __syncthreads();

    if (t < C) {
        int acc = 0;
#pragma unroll
        for (int ww = 0; ww < 8; ww++) { s_wbase[ww][t] = acc; acc += s_whist[ww][t]; }
        s_hist[t] = acc;
    }
    __syncthreads();
    if (t == 0) {
        int acc = 0;
#pragma unroll
        for (int cc = 0; cc < C; cc++) { s_off[cc] = acc; acc += s_hist[cc]; }
        s_off[C] = acc;
    }
    __syncthreads();

    int pos = s_off[c] + s_wbase[w][c] + lr;
    g_order[chunk * CHUNK_ROWS + pos] = t | (c << 16);
    if (t < 17) g_choff[chunk * 17 + t] = s_off[t];
    if (t < C)  g_chunkhist[chunk * C + t] = s_hist[t];
}

// ---------------- launch 2: pass 1 + (block 0) counts reduction ------------
// block = (chunk of 256 rows) x (quarter of the 512 dims), 128 threads.
// 1024 blocks -> ~7 blocks/SM, ~28 warps/SM. Register accumulate, flush on
// class change (block-uniform branch), 8-wide batched loads.
#define P1STEP(pp, vv)                                              \
    {                                                               \
        int cc = (pp) >> 16;                                        \
        if (cc != cur) {                                            \
            out[cur * DPQ] = make_float2(s, q);                     \
            s = 0.f; q = 0.f; cur = cc;                             \
        }                                                           \
        s += (vv); q = fmaf((vv), (vv), q);                         \
    }

__global__ __launch_bounds__(128) void k_pass1(const float* __restrict__ hidden) {
    __shared__ int s_off[17];
    __shared__ int s_cnt[128];
    int t = threadIdx.x;

    // block 0: reduce chunk histograms -> g_counts (8 segments x 16 classes)
    if (blockIdx.x == 0) {
        int c = t & 15, seg = t >> 4;            // seg 0..7
        int acc = 0;
        for (int ch = seg; ch < NCHUNK; ch += 8) acc += g_chunkhist[ch * C + c];
        s_cnt[t] = acc;
        __syncthreads();
        if (t < C) {
            int tot = 0;
#pragma unroll
            for (int s2 = 0; s2 < 8; s2++) tot += s_cnt[s2 * 16 + t];
            g_counts[t] = tot;
        }
        __syncthreads();
    }

    int quarter = blockIdx.x & 3;
    int chunk   = blockIdx.x >> 2;
    if (t < 17) s_off[t] = g_choff[chunk * 17 + t];
    __syncthreads();

    const float* base = hidden + (size_t)chunk * CHUNK_ROWS * D + quarter * DPQ + t;
    const int*   ord  = g_order + chunk * CHUNK_ROWS;
    float2*      out  = g_partial + (size_t)blockIdx.x * (C * DPQ) + t;

    float s = 0.f, q = 0.f;
    int cur = ord[0] >> 16;
#pragma unroll 1
    for (int k = 0; k < CHUNK_ROWS; k += 8) {
        int p0 = ord[k + 0], p1 = ord[k + 1], p2 = ord[k + 2], p3 = ord[k + 3];
        int p4 = ord[k + 4], p5 = ord[k + 5], p6 = ord[k + 6], p7 = ord[k + 7];
        float v0 = base[(size_t)(p0 & 0xffff) * D];
        float v1 = base[(size_t)(p1 & 0xffff) * D];
        float v2 = base[(size_t)(p2 & 0xffff) * D];
        float v3 = base[(size_t)(p3 & 0xffff) * D];
        float v4 = base[(size_t)(p4 & 0xffff) * D];
        float v5 = base[(size_t)(p5 & 0xffff) * D];
        float v6 = base[(size_t)(p6 & 0xffff) * D];
        float v7 = base[(size_t)(p7 & 0xffff) * D];
        P1STEP(p0, v0) P1STEP(p1, v1) P1STEP(p2, v2) P1STEP(p3, v3)
        P1STEP(p4, v4) P1STEP(p5, v5) P1STEP(p6, v6) P1STEP(p7, v7)
    }
    out[cur * DPQ] = make_float2(s, q);
#pragma unroll
    for (int cc = 0; cc < C; cc++)
        if (s_off[cc + 1] == s_off[cc]) out[cc * DPQ] = make_float2(0.f, 0.f);
}

// ---------------- launch 3: pass 2 stage A (wide coalesced) ----------------
// item = c*512 + dim (8192 items). 8 groups x 32 chunks each; blk = chunk*4+q.
__global__ __launch_bounds__(256) void k_pass2a() {
    int gid  = blockIdx.x * 256 + threadIdx.x;     // 0 .. 65535
    int item = gid & (C * D - 1);                  // 0 .. 8191
    int grp  = gid >> 13;                          // 0 .. 7
    int c    = item >> 9;
    int dim  = item & (D - 1);
    int quarter = dim >> 7;
    int tq      = dim & (DPQ - 1);
    const float2* p = g_partial + (size_t)c * DPQ + tq;
    float sx = 0.f, qq = 0.f;
#pragma unroll 8
    for (int k = 0; k < CPG; k++) {
        int chunk = grp * CPG + k;                 // 0 .. 255
        int blk   = (chunk << 2) | quarter;        // 0 .. 1023
        float2 v = p[(size_t)blk * (C * DPQ)];
        sx += v.x; qq += v.y;
    }
    g_pA[grp * (C * D) + item] = make_float2(sx, qq);
}

// ---------------- launch 4 (profiled): pair kernel (all-fp32 stats) --------
// Per-dim stats for classes i,j from the 512 KB L2-resident g_pA (8 groups),
// then x -> bitonic sort -> large-b asymptotic log-betainc on top-K -> sum.
// I_x(1/2,b) = erf(sqrt(s)) - sqrt(s)e^{-s}/(4b sqrt(pi)) + O(1/b^2),
// s = -b*log1p(-x). Monotone in x, so top-k commutes with the transform.
__global__ __launch_bounds__(D) void k_pairs(const int* __restrict__ dptr) {
    __shared__ float sx[D];
    __shared__ float sred[D];
    int t = threadIdx.x;

    int bid = blockIdx.x;
    int i = 0, rem = bid;
    while (rem >= C - 1 - i) { rem -= C - 1 - i; i++; }
    int j = i + 1 + rem;

    float ni = (float)g_counts[i], nj = (float)g_counts[j];
    float pc = ni + nj;
    float d2 = pc - 2.f;
    if (d2 == 0.f) d2 = 1e-5f;
    float b = d2 * 0.5f;

    float sxi = 0.f, qqi = 0.f, sxj = 0.f, qqj = 0.f;
#pragma unroll
    for (int g = 0; g < GRPS; g++) {
        float2 vi = g_pA[g * (C * D) + i * D + t];
        float2 vj = g_pA[g * (C * D) + j * D + t];
        sxi += vi.x; qqi += vi.y;
        sxj += vj.x; qqj += vj.y;
    }
    float mi = sxi / ni;
    float wi = qqi - sxi * mi;
    float mj = sxj / nj;
    float wj = qqj - sxj * mj;

    float hd   = (mi - mj) * 0.5f;
    float betw = hd * hd * pc;
    float x = betw / (betw + wi + wj);
    x = fminf(fmaxf(x, 1e-37f), 1.f - 1e-5f);
    sx[t] = x;
    __syncthreads();

    for (int k = 2; k <= D; k <<= 1) {
        for (int jj = k >> 1; jj > 0; jj >>= 1) {
            int ixj = t ^ jj;
            if (ixj > t) {
                float a0 = sx[t], b0 = sx[ixj];
                bool desc = ((t & k) == 0);
                if (desc ? (a0 < b0) : (a0 > b0)) { sx[t] = b0; sx[ixj] = a0; }
            }
            __syncthreads();
        }
    }

    int K = 64;
    if (dptr) {
        int kv = dptr[0];
        if (kv >= 1 && kv <= D) K = kv;
    }

    float val = 0.f;
    if (t < K) {
        float xv = sx[t];
        float s2 = -b * log1pf(-xv);               // s = -b ln(1-x)
        float rs = sqrtf(s2);
        const float inv_sqrtpi = 0.5641895835477563f;  // 1/sqrt(pi)
        float I = erff(rs) - rs * expf(-s2) * (inv_sqrtpi * 0.25f / b);
        I = fminf(fmaxf(I, 1e-38f), 1.f);
        val = logf(I);
    }
    sred[t] = val;
    __syncthreads();
    for (int s = D / 2; s > 0; s >>= 1) {
        if (t < s) sred[t] += sred[t + s];
        __syncthreads();
    }
    if (t == 0) g_pairsum[bid] = (double)sred[0];
}

// ---------------- launch 5: final scalar reduce -----------------------------
__global__ void k_final(float* out) {
    __shared__ double sr[128];
    int t = threadIdx.x;
    sr[t] = (t < NPAIRS) ? g_pairsum[t] : 0.0;
    __syncthreads();
    for (int s = 64; s > 0; s >>= 1) {
        if (t < s) sr[t] += sr[t + s];
        __syncthreads();
    }
    if (t == 0) out[0] = (float)(-sr[0]);
}

// ---------------- launch ----------------
extern "C" void kernel_launch(void* const* d_in, const int* in_sizes, int n_in,
                              void* d_out, int out_size) {
    const float* hidden = (const float*)d_in[0];
    const int*   ids32  = (const int*)d_in[1];
    const int*   dptr   = (n_in > 2) ? (const int*)d_in[2] : nullptr;

    int N = in_sizes[0] / D;            // 65536

    k_order <<<NCHUNK, 256>>>(ids32, N);                 // launch 1
    k_pass1 <<<PBLK, 128>>>(hidden);                     // launch 2
    k_pass2a<<<(GRPS * C * D) / 256, 256>>>();           // launch 3
    k_pairs <<<NPAIRS, D>>>(dptr);                       // launch 4 (profiled)
    k_final <<<1, 128>>>((float*)d_out);                 // launch 5
}